// round 11
// baseline (speedup 1.0000x reference)
#include <cuda_runtime.h>
#include <cuda_bf16.h>
#include <cstdint>

#define EMBED 1024
#define HID   128
#define NQ    65536
#define NP    512
#define MT    128          // M rows per CTA
#define KC    32           // K elems per pipeline stage
#define NITER (EMBED / KC) // 32
#define STAGES 3
#define APAD 36            // fp32 per A smem row (16B-aligned stride: 144B)
#define BPAD 40            // bf16 per B smem row (80B stride -> conflict-free frag reads)
#define A_STAGE_FLOATS (MT * APAD)        // 4608 floats = 18432 B
#define B_STAGE_HALFS  (HID * BPAD)       // 5120 bf16  = 10240 B
#define DYN_SMEM (STAGES * (A_STAGE_FLOATS * 4 + B_STAGE_HALFS * 2))  // 86016 B

// Scratch: W1 top half transposed to bf16 [n][k]; Pb = proto @ W1_bot + b1; argmin idx.
__device__ __align__(16) __nv_bfloat16 g_W1t[HID * EMBED];
__device__ __align__(16) float g_Pb[NP * HID];
__device__ int g_idx[NQ];

// ---------------------------------------------------------------------------
__device__ __forceinline__ uint32_t smem_u32(const void* p) {
    uint32_t a;
    asm("{ .reg .u64 t; cvta.to.shared.u64 t, %1; cvt.u32.u64 %0, t; }" : "=r"(a) : "l"(p));
    return a;
}
__device__ __forceinline__ void cp_async16(uint32_t dst, const void* src) {
    asm volatile("cp.async.cg.shared.global [%0], [%1], 16;" :: "r"(dst), "l"(src) : "memory");
}
#define CP_COMMIT() asm volatile("cp.async.commit_group;" ::: "memory")
#define CP_WAIT1()  asm volatile("cp.async.wait_group 1;" ::: "memory")

__device__ __forceinline__ uint32_t cvt_bf2(float hi, float lo) {
    uint32_t r;
    asm("cvt.rn.bf16x2.f32 %0, %1, %2;" : "=r"(r) : "f"(hi), "f"(lo));
    return r;
}

// ---------------------------------------------------------------------------
// Kernel 1: coalesced tile transpose W1_top (fp32 [k][n]) -> g_W1t (bf16 [n][k])
// grid (32, 4), block (32, 8)
// ---------------------------------------------------------------------------
__global__ void w1t_kernel(const float* __restrict__ W1) {
    __shared__ float tile[32][33];
    int kb = blockIdx.x * 32, nb = blockIdx.y * 32;
    int tx = threadIdx.x, ty = threadIdx.y;
#pragma unroll
    for (int r = ty; r < 32; r += 8)
        tile[r][tx] = W1[(size_t)(kb + r) * HID + nb + tx];       // coalesced read
    __syncthreads();
#pragma unroll
    for (int r = ty; r < 32; r += 8)
        g_W1t[(size_t)(nb + r) * EMBED + kb + tx] = __float2bfloat16(tile[tx][r]);  // coalesced write
}

// ---------------------------------------------------------------------------
// Kernel 2: Pb[p][j] = proto[p] @ W1_bottom[:, j] + b1[j]
// ---------------------------------------------------------------------------
__global__ void proto_kernel(const float* __restrict__ proto,
                             const float* __restrict__ W1,
                             const float* __restrict__ b1) {
    __shared__ float sp[4 * EMBED];
    __shared__ float spart[4][HID];
    int t  = threadIdx.x;
    int j  = t & (HID - 1);
    int kh = t >> 7;
    int p0 = blockIdx.x * 4;

    for (int i = t * 4; i < 4 * EMBED; i += 256 * 4)
        *(float4*)(sp + i) = *(const float4*)(proto + (size_t)p0 * EMBED + i);
    __syncthreads();

    float a0 = 0.f, a1 = 0.f, a2 = 0.f, a3 = 0.f;
    int kbeg = kh * (EMBED / 2);
#pragma unroll 4
    for (int k = kbeg; k < kbeg + EMBED / 2; k++) {
        float w = W1[(size_t)(EMBED + k) * HID + j];
        a0 += sp[0 * EMBED + k] * w;
        a1 += sp[1 * EMBED + k] * w;
        a2 += sp[2 * EMBED + k] * w;
        a3 += sp[3 * EMBED + k] * w;
    }
    if (kh == 1) { spart[0][j] = a0; spart[1][j] = a1; spart[2][j] = a2; spart[3][j] = a3; }
    __syncthreads();
    if (kh == 0) {
        float bb = b1[j];
        g_Pb[(size_t)(p0 + 0) * HID + j] = a0 + spart[0][j] + bb;
        g_Pb[(size_t)(p0 + 1) * HID + j] = a1 + spart[1][j] + bb;
        g_Pb[(size_t)(p0 + 2) * HID + j] = a2 + spart[2][j] + bb;
        g_Pb[(size_t)(p0 + 3) * HID + j] = a3 + spart[3][j] + bb;
    }
}

// ---------------------------------------------------------------------------
// Kernel 3: streaming argmin — one warp per query row.
// ---------------------------------------------------------------------------
__global__ __launch_bounds__(256)
void argmin_kernel(const float* __restrict__ dist) {
    int warp = threadIdx.x >> 5, lane = threadIdx.x & 31;
    int row  = blockIdx.x * 8 + warp;
    const float* r = dist + (size_t)row * NP;
    float best = 3.4e38f; int bi = 0;
#pragma unroll
    for (int it = 0; it < 4; it++) {
        int j = it * 128 + lane * 4;
        float4 v = *(const float4*)(r + j);
        if (v.x < best) { best = v.x; bi = j; }
        if (v.y < best) { best = v.y; bi = j + 1; }
        if (v.z < best) { best = v.z; bi = j + 2; }
        if (v.w < best) { best = v.w; bi = j + 3; }
    }
#pragma unroll
    for (int off = 16; off; off >>= 1) {
        float ov = __shfl_down_sync(0xffffffffu, best, off);
        int   oi = __shfl_down_sync(0xffffffffu, bi,   off);
        if (ov < best || (ov == best && oi < bi)) { best = ov; bi = oi; }
    }
    if (lane == 0) g_idx[row] = bi;
}

// ---------------------------------------------------------------------------
// Kernel 4: pipelined bf16 mma.sync GEMM (Q @ W1_top) + fused epilogue.
// CTA 128x128, 256 threads (8 warps: 4M x 2N, warp tile 32x64).
// cp.async 3-stage pipeline; A held fp32 in smem, converted at frag load.
// ---------------------------------------------------------------------------
__global__ __launch_bounds__(256, 2)
void gemm_kernel(const float* __restrict__ Q,
                 const float* __restrict__ W2,
                 const float* __restrict__ b2,
                 float* __restrict__ out) {
    extern __shared__ __align__(16) char dyn[];
    float*         As = (float*)dyn;                                   // 3 x 128 x APAD
    __nv_bfloat16* Bs = (__nv_bfloat16*)(dyn + STAGES * A_STAGE_FLOATS * 4);

    __shared__ float s_w2[HID];
    __shared__ float s_rowsum[MT];

    const int t = threadIdx.x, warp = t >> 5, lane = t & 31;
    const int m0 = blockIdx.x * MT;
    const uint32_t aSm = smem_u32(As);
    const uint32_t bSm = smem_u32(Bs);

    if (t < HID) s_w2[t] = W2[t];
    if (t < MT)  s_rowsum[t] = 0.f;

    // --- cp.async stage loaders ---
    const int ar = t >> 1, ah = t & 1;       // A: 2 threads/row, 4 chunks each
    const int bn = t >> 1, bh = t & 1;       // B: 2 threads/row, 2 chunks each
    const float*         qrow = Q + (size_t)(m0 + ar) * EMBED;
    const __nv_bfloat16* brow = g_W1t + (size_t)bn * EMBED;

    auto load_stage = [&](int c, int s) {
        const int k0 = c * KC;
        uint32_t aDst = aSm + s * A_STAGE_FLOATS * 4 + ar * (APAD * 4);
        uint32_t bDst = bSm + s * B_STAGE_HALFS * 2 + bn * (BPAD * 2);
#pragma unroll
        for (int j = 0; j < 4; j++) {
            int c16 = ah * 4 + j;                          // 0..7
            cp_async16(aDst + c16 * 16, qrow + k0 + c16 * 4);
        }
#pragma unroll
        for (int j = 0; j < 2; j++) {
            int c16 = bh * 2 + j;                          // 0..3
            cp_async16(bDst + c16 * 16, brow + k0 + c16 * 8);
        }
    };

    // --- accumulators + frag mapping ---
    float acc[2][8][4];
#pragma unroll
    for (int mi = 0; mi < 2; mi++)
#pragma unroll
        for (int ni = 0; ni < 8; ni++)
#pragma unroll
            for (int r = 0; r < 4; r++) acc[mi][ni][r] = 0.f;

    const int warpM = warp >> 1;   // rows warpM*32
    const int warpN = warp & 1;    // cols warpN*64
    const int g  = lane >> 2;      // 0..7
    const int qd = lane & 3;       // 0..3

    // --- pipeline prologue ---
    load_stage(0, 0); CP_COMMIT();
    load_stage(1, 1); CP_COMMIT();

    for (int c = 0; c < NITER; c++) {
        const int sc = c % STAGES;
        CP_WAIT1();                 // stage c resident
        __syncthreads();            // visible to all warps; stage c-1 free

        if (c + 2 < NITER) load_stage(c + 2, (c + 2) % STAGES);
        CP_COMMIT();

        const float*         A0 = As + sc * A_STAGE_FLOATS;
        const __nv_bfloat16* B0 = Bs + sc * B_STAGE_HALFS;

#pragma unroll
        for (int ks = 0; ks < 2; ks++) {
            const int ko = ks * 16;
            uint32_t a[2][4];
#pragma unroll
            for (int mi = 0; mi < 2; mi++) {
                const float* p1 = A0 + (warpM * 32 + mi * 16 + g) * APAD + ko + qd * 2;
                const float* p2 = p1 + 8 * APAD;
                float2 v;
                v = *(const float2*)(p1);     a[mi][0] = cvt_bf2(v.y, v.x);
                v = *(const float2*)(p2);     a[mi][1] = cvt_bf2(v.y, v.x);
                v = *(const float2*)(p1 + 8); a[mi][2] = cvt_bf2(v.y, v.x);
                v = *(const float2*)(p2 + 8); a[mi][3] = cvt_bf2(v.y, v.x);
            }
            uint32_t b[8][2];
#pragma unroll
            for (int ni = 0; ni < 8; ni++) {
                const __nv_bfloat16* pb = B0 + (warpN * 64 + ni * 8 + g) * BPAD + ko + qd * 2;
                b[ni][0] = *(const uint32_t*)(pb);
                b[ni][1] = *(const uint32_t*)(pb + 8);
            }
#pragma unroll
            for (int mi = 0; mi < 2; mi++)
#pragma unroll
                for (int ni = 0; ni < 8; ni++)
                    asm volatile(
                        "mma.sync.aligned.m16n8k16.row.col.f32.bf16.bf16.f32 "
                        "{%0,%1,%2,%3}, {%4,%5,%6,%7}, {%8,%9}, {%0,%1,%2,%3};\n"
                        : "+f"(acc[mi][ni][0]), "+f"(acc[mi][ni][1]),
                          "+f"(acc[mi][ni][2]), "+f"(acc[mi][ni][3])
                        : "r"(a[mi][0]), "r"(a[mi][1]), "r"(a[mi][2]), "r"(a[mi][3]),
                          "r"(b[ni][0]), "r"(b[ni][1]));
        }
        __syncthreads();            // done reading stage sc before it is refilled
    }

    // ---- epilogue: +Pb[idx], relu, * W2, row-reduce, sigmoid ----
#pragma unroll
    for (int mi = 0; mi < 2; mi++) {
#pragma unroll
        for (int rr = 0; rr < 2; rr++) {
            int rloc = warpM * 32 + mi * 16 + rr * 8 + g;
            const float* Pr = g_Pb + (size_t)g_idx[m0 + rloc] * HID;
            float s = 0.f;
#pragma unroll
            for (int ni = 0; ni < 8; ni++) {
                int cc = warpN * 64 + ni * 8 + qd * 2;
                float v0 = acc[mi][ni][rr * 2 + 0] + Pr[cc];
                float v1 = acc[mi][ni][rr * 2 + 1] + Pr[cc + 1];
                s += fmaxf(v0, 0.f) * s_w2[cc] + fmaxf(v1, 0.f) * s_w2[cc + 1];
            }
            atomicAdd(&s_rowsum[rloc], s);
        }
    }
    __syncthreads();
    if (t < MT) {
        float z = s_rowsum[t] + b2[0];
        out[m0 + t] = 1.f / (1.f + __expf(-z));
    }
}

// ---------------------------------------------------------------------------
extern "C" void kernel_launch(void* const* d_in, const int* in_sizes, int n_in,
                              void* d_out, int out_size) {
    const float* Q     = (const float*)d_in[0];   // [65536,1024]
    const float* proto = (const float*)d_in[1];   // [512,1024]
    const float* dist  = (const float*)d_in[2];   // [65536,512]
    const float* W1    = (const float*)d_in[3];   // [2048,128]
    const float* b1    = (const float*)d_in[4];   // [128]
    const float* W2    = (const float*)d_in[5];   // [128,1]
    const float* b2    = (const float*)d_in[6];   // [1]
    float* out = (float*)d_out;                   // [65536]

    static bool attr_set = false;
    if (!attr_set) {
        cudaFuncSetAttribute(gemm_kernel,
                             cudaFuncAttributeMaxDynamicSharedMemorySize, DYN_SMEM);
        attr_set = true;
    }

    w1t_kernel<<<dim3(EMBED / 32, HID / 32), dim3(32, 8)>>>(W1);
    proto_kernel<<<NP / 4, 256>>>(proto, W1, b1);
    argmin_kernel<<<NQ / 8, 256>>>(dist);
    gemm_kernel<<<NQ / MT, 256, DYN_SMEM>>>(Q, W2, b2, out);
}